// round 2
// baseline (speedup 1.0000x reference)
#include <cuda_runtime.h>

#define N_NODES   100000
#define N_EDGES   1600000
#define N_GRAPHS  5000
#define ND        16
#define ED        16
#define HID       20
#define H2        10
#define HP        (HID/2)   // 10 f32x2 pairs
#define H2P       (H2/2)    // 5 pairs

// Scratch
__device__ float g_x [N_NODES * HID];
__device__ float g_pa[N_NODES * HID];
__device__ float g_pb[N_NODES * HID];
__device__ float g_g [N_GRAPHS * H2];

// ---- packed f32x2 helpers -------------------------------------------------
__device__ __forceinline__ unsigned long long fma2(unsigned long long a,
                                                   unsigned long long b,
                                                   unsigned long long c) {
    unsigned long long d;
    asm("fma.rn.f32x2 %0, %1, %2, %3;" : "=l"(d) : "l"(a), "l"(b), "l"(c));
    return d;
}
__device__ __forceinline__ unsigned long long bcast2(float x) {
    unsigned long long d;
    asm("mov.b64 %0, {%1, %1};" : "=l"(d) : "f"(x));
    return d;
}
__device__ __forceinline__ float2 unpack2(unsigned long long v) {
    float2 r;
    asm("mov.b64 {%0, %1}, %2;" : "=f"(r.x), "=f"(r.y) : "l"(v));
    return r;
}

// ---------------------------------------------------------------------------
// Kernel 1: per-node projections pa = A@Wa, pb = A@Wb  (+ fused zeroing)
// ---------------------------------------------------------------------------
__global__ void node_proj_kernel(const float* __restrict__ node_attr,
                                 const float* __restrict__ W_msg) {
    __shared__ __align__(8) float sWa[ND * HID];
    __shared__ __align__(8) float sWb[ND * HID];
    for (int i = threadIdx.x; i < ND * HID; i += blockDim.x) {
        sWa[i] = W_msg[i];
        sWb[i] = W_msg[ND * HID + i];
    }
    __syncthreads();
    const unsigned long long* wa2 = (const unsigned long long*)sWa;
    const unsigned long long* wb2 = (const unsigned long long*)sWb;

    int n = blockIdx.x * blockDim.x + threadIdx.x;

    // fused zero of g_g (50000 floats) by the first threads
    if (n < (N_GRAPHS * H2) / 4)
        ((float4*)g_g)[n] = make_float4(0.f, 0.f, 0.f, 0.f);

    if (n >= N_NODES) return;

    // fused zero of this node's g_x row
    {
        const float4 z = make_float4(0.f, 0.f, 0.f, 0.f);
        float4* xr = (float4*)(g_x + (size_t)n * HID);
#pragma unroll
        for (int q = 0; q < 5; q++) xr[q] = z;
    }

    float a[ND];
    const float4* ap = (const float4*)(node_attr + (size_t)n * ND);
#pragma unroll
    for (int q = 0; q < 4; q++) {
        float4 v = ap[q];
        a[4*q+0] = v.x; a[4*q+1] = v.y; a[4*q+2] = v.z; a[4*q+3] = v.w;
    }

    unsigned long long acc[HP];
#pragma unroll
    for (int p = 0; p < HP; p++) acc[p] = 0ull;
#pragma unroll
    for (int k = 0; k < ND; k++) {
        unsigned long long ak = bcast2(a[k]);
#pragma unroll
        for (int p = 0; p < HP; p++) acc[p] = fma2(ak, wa2[k * HP + p], acc[p]);
    }
    {
        float2* pa = (float2*)(g_pa + (size_t)n * HID);
#pragma unroll
        for (int p = 0; p < HP; p++) pa[p] = unpack2(acc[p]);
    }

#pragma unroll
    for (int p = 0; p < HP; p++) acc[p] = 0ull;
#pragma unroll
    for (int k = 0; k < ND; k++) {
        unsigned long long ak = bcast2(a[k]);
#pragma unroll
        for (int p = 0; p < HP; p++) acc[p] = fma2(ak, wb2[k * HP + p], acc[p]);
    }
    {
        float2* pb = (float2*)(g_pb + (size_t)n * HID);
#pragma unroll
        for (int p = 0; p < HP; p++) pb[p] = unpack2(acc[p]);
    }
}

// ---------------------------------------------------------------------------
// Kernel 2: edge message + scatter-sum
// ---------------------------------------------------------------------------
__global__ __launch_bounds__(256) void edge_kernel(
        const int*   __restrict__ edge_index,
        const float* __restrict__ edge_attr,
        const float* __restrict__ W_msg,
        const float* __restrict__ b_msg) {
    __shared__ __align__(8) float sWe[ED * HID];
    __shared__ __align__(8) float sb[HID];
    for (int i = threadIdx.x; i < ED * HID; i += blockDim.x)
        sWe[i] = W_msg[2 * ND * HID + i];
    for (int i = threadIdx.x; i < HID; i += blockDim.x)
        sb[i] = b_msg[i];
    __syncthreads();
    const unsigned long long* we2 = (const unsigned long long*)sWe;
    const unsigned long long* sb2 = (const unsigned long long*)sb;

    int e = blockIdx.x * blockDim.x + threadIdx.x;
    if (e >= N_EDGES) return;

    int src = __ldg(edge_index + e);
    int dst = __ldg(edge_index + N_EDGES + e);

    // issue gathers early (independent of matmul)
    const float4* pap = (const float4*)(g_pa + (size_t)src * HID);
    const float4* pbp = (const float4*)(g_pb + (size_t)dst * HID);
    float4 va[5], vb[5];
#pragma unroll
    for (int q = 0; q < 5; q++) { va[q] = pap[q]; vb[q] = pbp[q]; }

    unsigned long long acc[HP];
#pragma unroll
    for (int p = 0; p < HP; p++) acc[p] = sb2[p];

    const float4* ep = (const float4*)(edge_attr + (size_t)e * ED);
#pragma unroll
    for (int q = 0; q < 4; q++) {
        float4 v = ep[q];
        float ek[4] = {v.x, v.y, v.z, v.w};
#pragma unroll
        for (int t = 0; t < 4; t++) {
            unsigned long long b = bcast2(ek[t]);
#pragma unroll
            for (int p = 0; p < HP; p++)
                acc[p] = fma2(b, we2[(4*q + t) * HP + p], acc[p]);
        }
    }

    float m[HID];
#pragma unroll
    for (int p = 0; p < HP; p++) {
        float2 t = unpack2(acc[p]);
        m[2*p] = t.x; m[2*p+1] = t.y;
    }
#pragma unroll
    for (int q = 0; q < 5; q++) {
        m[4*q+0] += va[q].x + vb[q].x;
        m[4*q+1] += va[q].y + vb[q].y;
        m[4*q+2] += va[q].z + vb[q].z;
        m[4*q+3] += va[q].w + vb[q].w;
    }
#pragma unroll
    for (int j = 0; j < HID; j++) m[j] = fmaxf(m[j], 0.f);

    float* xr = g_x + (size_t)dst * HID;
#pragma unroll
    for (int q = 0; q < 5; q++) {
        asm volatile("red.global.add.v4.f32 [%0], {%1,%2,%3,%4};"
                     :: "l"(xr + 4*q),
                        "f"(m[4*q]), "f"(m[4*q+1]), "f"(m[4*q+2]), "f"(m[4*q+3])
                     : "memory");
    }
}

// ---------------------------------------------------------------------------
// Kernel 3: node MLP + graph pooling
// ---------------------------------------------------------------------------
__global__ __launch_bounds__(128) void node_mlp_kernel(
        const int*   __restrict__ batch,
        const float* __restrict__ W1,
        const float* __restrict__ b1) {
    __shared__ __align__(8) float sW[HID * H2];
    __shared__ __align__(8) float sb[H2];
    for (int i = threadIdx.x; i < HID * H2; i += blockDim.x) sW[i] = W1[i];
    for (int i = threadIdx.x; i < H2; i += blockDim.x) sb[i] = b1[i];
    __syncthreads();
    const unsigned long long* w2 = (const unsigned long long*)sW;
    const unsigned long long* sb2 = (const unsigned long long*)sb;

    int n = blockIdx.x * blockDim.x + threadIdx.x;
    if (n >= N_NODES) return;

    int b = __ldg(batch + n);     // issue first

    float x[HID];
    const float4* xp = (const float4*)(g_x + (size_t)n * HID);
#pragma unroll
    for (int q = 0; q < 5; q++) {
        float4 v = xp[q];
        x[4*q+0] = v.x; x[4*q+1] = v.y; x[4*q+2] = v.z; x[4*q+3] = v.w;
    }

    unsigned long long acc[H2P];
#pragma unroll
    for (int p = 0; p < H2P; p++) acc[p] = sb2[p];
#pragma unroll
    for (int k = 0; k < HID; k++) {
        unsigned long long xk = bcast2(x[k]);
#pragma unroll
        for (int p = 0; p < H2P; p++) acc[p] = fma2(xk, w2[k * H2P + p], acc[p]);
    }

    float y[H2];
#pragma unroll
    for (int p = 0; p < H2P; p++) {
        float2 t = unpack2(acc[p]);
        y[2*p]   = fmaxf(t.x, 0.f);
        y[2*p+1] = fmaxf(t.y, 0.f);
    }

    float* gr = g_g + (size_t)b * H2;
#pragma unroll
    for (int q = 0; q < 5; q++) {
        asm volatile("red.global.add.v2.f32 [%0], {%1,%2};"
                     :: "l"(gr + 2*q), "f"(y[2*q]), "f"(y[2*q+1])
                     : "memory");
    }
}

// ---------------------------------------------------------------------------
// Kernel 4: graph MLP
// ---------------------------------------------------------------------------
__global__ void graph_mlp_kernel(const float* __restrict__ W2,
                                 const float* __restrict__ b2,
                                 const float* __restrict__ W3,
                                 const float* __restrict__ b3,
                                 float* __restrict__ out) {
    __shared__ float sW2[H2 * H2];
    __shared__ float sb2[H2];
    __shared__ float sW3[H2];
    __shared__ float sb3;
    for (int i = threadIdx.x; i < H2 * H2; i += blockDim.x) sW2[i] = W2[i];
    if (threadIdx.x < H2) { sb2[threadIdx.x] = b2[threadIdx.x]; sW3[threadIdx.x] = W3[threadIdx.x]; }
    if (threadIdx.x == 0) sb3 = b3[0];
    __syncthreads();

    int g = blockIdx.x * blockDim.x + threadIdx.x;
    if (g >= N_GRAPHS) return;

    float v[H2];
    const float2* gp = (const float2*)(g_g + (size_t)g * H2);
#pragma unroll
    for (int q = 0; q < 5; q++) {
        float2 t = gp[q];
        v[2*q] = t.x; v[2*q+1] = t.y;
    }

    float o = sb3;
#pragma unroll
    for (int j = 0; j < H2; j++) {
        float h = sb2[j];
#pragma unroll
        for (int k = 0; k < H2; k++) h = fmaf(v[k], sW2[k * H2 + j], h);
        o = fmaf(fmaxf(h, 0.f), sW3[j], o);
    }
    out[g] = o;
}

// ---------------------------------------------------------------------------
extern "C" void kernel_launch(void* const* d_in, const int* in_sizes, int n_in,
                              void* d_out, int out_size) {
    const int*   edge_index = (const int*)  d_in[0];
    const float* node_attr  = (const float*)d_in[1];
    const float* edge_attr  = (const float*)d_in[2];
    const int*   batch      = (const int*)  d_in[3];
    const float* W_msg      = (const float*)d_in[4];
    const float* b_msg      = (const float*)d_in[5];
    const float* W1         = (const float*)d_in[6];
    const float* b1         = (const float*)d_in[7];
    const float* W2         = (const float*)d_in[8];
    const float* b2         = (const float*)d_in[9];
    const float* W3         = (const float*)d_in[10];
    const float* b3         = (const float*)d_in[11];
    float* out = (float*)d_out;

    node_proj_kernel<<<(N_NODES + 255) / 256, 256>>>(node_attr, W_msg);
    edge_kernel<<<(N_EDGES + 255) / 256, 256>>>(edge_index, edge_attr, W_msg, b_msg);
    node_mlp_kernel<<<(N_NODES + 127) / 128, 128>>>(batch, W1, b1);
    graph_mlp_kernel<<<(N_GRAPHS + 255) / 256, 256>>>(W2, b2, W3, b3, out);
}